// round 7
// baseline (speedup 1.0000x reference)
#include <cuda_runtime.h>
#include <math.h>

// ODE-RNN persistent kernel, round 7:
//  - NT=1024 (8 warps/SMSP): MLP GEMMs k-split across warp pairs (warp w:
//    kt 0..15, warp w+16: kt 16..31 -> smem partial, lower warp reduces +
//    fused epilogue). Halves per-warp serial GEMM depth, doubles latency hiding.
//  - GRU m-split 4-way. Grid 64 CTAs x MB=16 (L2 traffic unchanged).

#define NT 1024
#define MBR 16
#define NCTA 64
#define T_LEN 200
#define XS 24   // activation row stride in floats
#define PS 18   // partial buffer row stride

typedef unsigned long long ull;

__device__ float g_WihT[16 * 768 * 4];
__device__ float g_WhhT[64 * 768 * 4];
// MLP tf32 fragment-packed weights: [nt(16)][kt(32)][lane(32)][a0..a3]
__device__ unsigned g_W1F[16 * 32 * 32 * 4];
__device__ unsigned g_W2F[16 * 32 * 32 * 4];
__device__ unsigned g_W3F[16 * 32 * 32 * 4];
__device__ float g_W1last[256];

__device__ __forceinline__ unsigned tf32r(float f) {
    unsigned u;
    asm("cvt.rna.tf32.f32 %0, %1;" : "=r"(u) : "f"(f));
    return u;
}

__global__ void prep_kernel(const float* __restrict__ W_ih,
                            const float* __restrict__ W_hh,
                            const float* __restrict__ W1,
                            const float* __restrict__ W2,
                            const float* __restrict__ W3) {
    int idx = blockIdx.x * blockDim.x + threadIdx.x;
    int stride = gridDim.x * blockDim.x;
    for (int t = idx; t < 16 * 768 * 4; t += stride) {
        int j = t & 3, nk = t >> 2;
        int n = nk % 768, k4 = nk / 768;
        g_WihT[t] = W_ih[n * 64 + k4 * 4 + j];
    }
    for (int t = idx; t < 64 * 768 * 4; t += stride) {
        int j = t & 3, nk = t >> 2;
        int n = nk % 768, k4 = nk / 768;
        g_WhhT[t] = W_hh[n * 256 + k4 * 4 + j];
    }
    for (int tI = idx; tI < 16 * 32 * 32; tI += stride) {
        int l = tI & 31, kt = (tI >> 5) & 31, nt = tI >> 10;
        int gid = l >> 2, tig = l & 3;
        int r0 = nt * 16 + gid, r1 = r0 + 8;
        int c0 = kt * 8 + tig, c1 = c0 + 4;
        g_W1F[tI * 4 + 0] = tf32r(W1[r0 * 257 + c0]);
        g_W1F[tI * 4 + 1] = tf32r(W1[r1 * 257 + c0]);
        g_W1F[tI * 4 + 2] = tf32r(W1[r0 * 257 + c1]);
        g_W1F[tI * 4 + 3] = tf32r(W1[r1 * 257 + c1]);
        g_W2F[tI * 4 + 0] = tf32r(W2[r0 * 256 + c0]);
        g_W2F[tI * 4 + 1] = tf32r(W2[r1 * 256 + c0]);
        g_W2F[tI * 4 + 2] = tf32r(W2[r0 * 256 + c1]);
        g_W2F[tI * 4 + 3] = tf32r(W2[r1 * 256 + c1]);
        g_W3F[tI * 4 + 0] = tf32r(W3[r0 * 256 + c0]);
        g_W3F[tI * 4 + 1] = tf32r(W3[r1 * 256 + c0]);
        g_W3F[tI * 4 + 2] = tf32r(W3[r0 * 256 + c1]);
        g_W3F[tI * 4 + 3] = tf32r(W3[r1 * 256 + c1]);
    }
    for (int n = idx; n < 256; n += stride) g_W1last[n] = W1[n * 257 + 256];
}

__device__ __forceinline__ float sigm(float v) {
    return 1.0f / (1.0f + __expf(-v));
}
__device__ __forceinline__ float tanha(float v) {
    float r;
    asm("tanh.approx.f32 %0, %1;" : "=f"(r) : "f"(v));
    return r;
}
__device__ __forceinline__ ull pk2(float a, float b) {
    ull r;
    asm("mov.b64 %0, {%1, %2};" : "=l"(r) : "f"(a), "f"(b));
    return r;
}
__device__ __forceinline__ ull ffma2(ull a, ull b, ull c) {
    ull d;
    asm("fma.rn.f32x2 %0, %1, %2, %3;" : "=l"(d) : "l"(a), "l"(b), "l"(c));
    return d;
}

#define MMA_TF32(c0, c1, c2, c3, A0, A1, A2, A3, B0, B1)                      \
    asm volatile(                                                             \
        "mma.sync.aligned.m16n8k8.row.col.f32.tf32.tf32.f32 "                 \
        "{%0,%1,%2,%3}, {%4,%5,%6,%7}, {%8,%9}, {%0,%1,%2,%3};"               \
        : "+f"(c0), "+f"(c1), "+f"(c2), "+f"(c3)                              \
        : "r"(A0), "r"(A1), "r"(A2), "r"(A3), "r"(B0), "r"(B1))

// One MLP GEMM: D[256][16] = W @ xs. Warp pair (w, w+16) splits K.
// Upper half writes partials; lower half reduces + epilogue.
// EPI: 0 = bias(+tt*w1l)+tanh -> dst ; 1..4 = RK4 stage update fused.
template<int EPI>
__device__ __forceinline__ void gemm16(const unsigned* __restrict__ WF,
                                       const float* __restrict__ xs,
                                       float* __restrict__ part,
                                       float* __restrict__ dst,
                                       const float* __restrict__ bias,
                                       const float* __restrict__ w1l,
                                       float tt, bool tcol,
                                       float* __restrict__ hT,
                                       float* __restrict__ yT,
                                       float* __restrict__ ka,
                                       const float* __restrict__ b3s,
                                       float dt) {
    const int warp = threadIdx.x >> 5;
    const int nt = warp & 15;
    const int kh = warp >> 4;     // 0 = lower K half, 1 = upper K half
    const int lane = threadIdx.x & 31;
    const int gid = lane >> 2, tig = lane & 3;
    float c00 = 0.f, c01 = 0.f, c02 = 0.f, c03 = 0.f;
    float c10 = 0.f, c11 = 0.f, c12 = 0.f, c13 = 0.f;
    const float4* __restrict__ wp =
        reinterpret_cast<const float4*>(WF) + (nt * 32 * 32 + kh * 16 * 32 + lane);
    const float* __restrict__ bp = xs + tig * XS + gid + kh * 16 * 8 * XS;
#pragma unroll 4
    for (int kt = 0; kt < 16; ++kt) {
        float4 af = wp[kt * 32];
        unsigned A0 = __float_as_uint(af.x), A1 = __float_as_uint(af.y);
        unsigned A2 = __float_as_uint(af.z), A3 = __float_as_uint(af.w);
        const float* __restrict__ b = bp + kt * 8 * XS;
        unsigned B0 = tf32r(b[0]);
        unsigned B1 = tf32r(b[4 * XS]);
        unsigned B2 = tf32r(b[8]);
        unsigned B3 = tf32r(b[4 * XS + 8]);
        MMA_TF32(c00, c01, c02, c03, A0, A1, A2, A3, B0, B1);
        MMA_TF32(c10, c11, c12, c13, A0, A1, A2, A3, B2, B3);
    }
    const int r0 = nt * 16 + gid, r1 = r0 + 8;
    const int mc = 2 * tig;
    if (kh == 1) {
        *reinterpret_cast<float2*>(&part[r0 * PS + mc])     = make_float2(c00, c01);
        *reinterpret_cast<float2*>(&part[r1 * PS + mc])     = make_float2(c02, c03);
        *reinterpret_cast<float2*>(&part[r0 * PS + 8 + mc]) = make_float2(c10, c11);
        *reinterpret_cast<float2*>(&part[r1 * PS + 8 + mc]) = make_float2(c12, c13);
    }
    __syncthreads();
    if (kh == 0) {
        float2 q;
        q = *reinterpret_cast<float2*>(&part[r0 * PS + mc]);     c00 += q.x; c01 += q.y;
        q = *reinterpret_cast<float2*>(&part[r1 * PS + mc]);     c02 += q.x; c03 += q.y;
        q = *reinterpret_cast<float2*>(&part[r0 * PS + 8 + mc]); c10 += q.x; c11 += q.y;
        q = *reinterpret_cast<float2*>(&part[r1 * PS + 8 + mc]); c12 += q.x; c13 += q.y;
        if (EPI == 0) {
            float bb0 = bias[r0], bb1 = bias[r1];
            if (tcol) { bb0 += tt * w1l[r0]; bb1 += tt * w1l[r1]; }
            *reinterpret_cast<float2*>(&dst[r0 * XS + mc]) =
                make_float2(tanha(bb0 + c00), tanha(bb0 + c01));
            *reinterpret_cast<float2*>(&dst[r1 * XS + mc]) =
                make_float2(tanha(bb1 + c02), tanha(bb1 + c03));
            *reinterpret_cast<float2*>(&dst[r0 * XS + 8 + mc]) =
                make_float2(tanha(bb0 + c10), tanha(bb0 + c11));
            *reinterpret_cast<float2*>(&dst[r1 * XS + 8 + mc]) =
                make_float2(tanha(bb1 + c12), tanha(bb1 + c13));
        } else {
            float b0 = b3s[r0], b1 = b3s[r1];
#pragma unroll
            for (int q2 = 0; q2 < 4; ++q2) {
                int r = (q2 & 1) ? r1 : r0;
                int m = ((q2 >> 1) ? 8 : 0) + mc;
                float f0 = ((q2 & 1) ? b1 : b0) +
                           (q2 == 0 ? c00 : q2 == 1 ? c02 : q2 == 2 ? c10 : c12);
                float f1 = ((q2 & 1) ? b1 : b0) +
                           (q2 == 0 ? c01 : q2 == 1 ? c03 : q2 == 2 ? c11 : c13);
                float2 h = *reinterpret_cast<float2*>(&hT[r * XS + m]);
                if (EPI == 1) {
                    *reinterpret_cast<float2*>(&ka[r * XS + m]) = make_float2(f0, f1);
                    float c = 0.5f * dt;
                    *reinterpret_cast<float2*>(&yT[r * XS + m]) =
                        make_float2(h.x + c * f0, h.y + c * f1);
                } else if (EPI == 2 || EPI == 3) {
                    float2 kk = *reinterpret_cast<float2*>(&ka[r * XS + m]);
                    *reinterpret_cast<float2*>(&ka[r * XS + m]) =
                        make_float2(kk.x + 2.f * f0, kk.y + 2.f * f1);
                    float c = (EPI == 2) ? 0.5f * dt : dt;
                    *reinterpret_cast<float2*>(&yT[r * XS + m]) =
                        make_float2(h.x + c * f0, h.y + c * f1);
                } else {
                    float2 kk = *reinterpret_cast<float2*>(&ka[r * XS + m]);
                    float c = dt * (1.0f / 6.0f);
                    *reinterpret_cast<float2*>(&hT[r * XS + m]) =
                        make_float2(h.x + c * (kk.x + f0), h.y + c * (kk.y + f1));
                }
            }
        }
    }
}

// GRU GEMM, fp32 FFMA2, 4 m per thread (mq = tid>>8), xs row stride XS.
template<int K>
__device__ __forceinline__ void gru_mm(const float* __restrict__ WT4,
                                       const float* __restrict__ bias,
                                       const float* __restrict__ xs,
                                       float* __restrict__ ys, int N) {
    const int lane_n = threadIdx.x & 255;
    const int mq = threadIdx.x >> 8;   // 0..3
    const float* __restrict__ xb = xs + mq * 4;
    for (int n = lane_n; n < N; n += 256) {
        float a0 = bias[n];
        ull acc0 = 0ULL, acc1 = 0ULL;
        const float4* __restrict__ wp = reinterpret_cast<const float4*>(WT4) + n;
#pragma unroll 4
        for (int k4 = 0; k4 < K / 4; ++k4) {
            float4 w = wp[(size_t)k4 * N];
            const float* __restrict__ xr = xb + (k4 * 4) * XS;
#pragma unroll
            for (int kk = 0; kk < 4; ++kk) {
                float wv = (kk == 0 ? w.x : kk == 1 ? w.y : kk == 2 ? w.z : w.w);
                ull wd = pk2(wv, wv);
                float4 xa = *reinterpret_cast<const float4*>(xr + kk * XS);
                acc0 = ffma2(wd, pk2(xa.x, xa.y), acc0);
                acc1 = ffma2(wd, pk2(xa.z, xa.w), acc1);
            }
        }
        float2 p0 = *reinterpret_cast<float2*>(&acc0);
        float2 p1 = *reinterpret_cast<float2*>(&acc1);
        *reinterpret_cast<float4*>(ys + n * 16 + mq * 4) =
            make_float4(a0 + p0.x, a0 + p0.y, a0 + p1.x, a0 + p1.y);
    }
}

__global__ void __launch_bounds__(NT, 1)
odernn_kernel(const float* __restrict__ x,
              const float* __restrict__ t,
              const float* __restrict__ mask,
              const float* __restrict__ b_ih,
              const float* __restrict__ b_hh,
              const float* __restrict__ b1,
              const float* __restrict__ b2,
              const float* __restrict__ b3,
              float* __restrict__ out) {
    extern __shared__ float sm[];
    float* xT = sm;              // 64*24  = 1536
    float* hT = sm + 1536;       // 256*24 = 6144
    float* U  = sm + 7680;       // union region 24576 floats
    float* gi = U;               // 768*16 = 12288 (GRU phase)
    float* gh = U + 12288;       // 12288
    float* yT = U;               // 6144 (RK4 phase)
    float* a1 = U + 6144;        // 6144
    float* a2 = U + 12288;       // 6144
    float* ka = U + 18432;       // 6144
    float* bihs = sm + 32256;    // 768
    float* bhhs = bihs + 768;    // 768
    float* b1s  = bhhs + 768;    // 256
    float* b2s  = b1s + 256;     // 256
    float* b3s  = b2s + 256;     // 256
    float* w1ls = b3s + 256;     // 256
    float* part = sm + 34816;    // 256*18 = 4608
    // total 39424 floats = 157696 bytes

    const int tid = threadIdx.x;
    const int m0 = blockIdx.x * MBR;

    for (int idx = tid; idx < 768; idx += NT) { bihs[idx] = b_ih[idx]; bhhs[idx] = b_hh[idx]; }
    for (int idx = tid; idx < 256; idx += NT) {
        b1s[idx] = b1[idx]; b2s[idx] = b2[idx]; b3s[idx] = b3[idx];
        w1ls[idx] = g_W1last[idx];
    }
    for (int idx = tid; idx < 256 * XS; idx += NT) hT[idx] = 0.0f;
    __syncthreads();

    for (int i = 0; i < T_LEN; ++i) {
        for (int idx = tid; idx < 64 * MBR; idx += NT) {
            int k = idx & 63, m = idx >> 6;
            xT[k * XS + m] = x[((size_t)(m0 + m) * T_LEN + i) * 64 + k];
        }
        __syncthreads();

        gru_mm<64>(g_WihT, bihs, xT, gi, 768);
        gru_mm<256>(g_WhhT, bhhs, hT, gh, 768);
        __syncthreads();

        // gate pointwise: m = tid&15, n = (tid>>4) + 64j
        {
            const int pm = tid & 15;
            const int pn0 = tid >> 4;
#pragma unroll
            for (int j = 0; j < 4; ++j) {
                int n = pn0 + j * 64;
                float ir = gi[n * 16 + pm];
                float iz = gi[(256 + n) * 16 + pm];
                float in_ = gi[(512 + n) * 16 + pm];
                float hr = gh[n * 16 + pm];
                float hz = gh[(256 + n) * 16 + pm];
                float hn = gh[(512 + n) * 16 + pm];
                float h = hT[n * XS + pm];
                float r = sigm(ir + hr);
                float z = sigm(iz + hz);
                float nn = tanhf(in_ + r * hn);
                float hnew = (1.0f - z) * nn + z * h;
                float mk = mask[(size_t)(m0 + pm) * T_LEN + i];
                float hobs = mk * hnew + (1.0f - mk) * h;
                hT[n * XS + pm] = hobs;
                out[((size_t)(m0 + pm) * T_LEN + i) * 256 + n] = hobs;
            }
        }
        __syncthreads();

        if (i == T_LEN - 1) break;

        float t0v = t[i], t1v = t[i + 1];
        float dt = (t1v - t0v) * 0.25f;
        float tt = t0v;
        for (int sub = 0; sub < 4; ++sub) {
            // stage 1: f(tt, hT)
            gemm16<0>(g_W1F, hT, part, a1, b1s, w1ls, tt, true, 0, 0, 0, 0, 0.f); __syncthreads();
            gemm16<0>(g_W2F, a1, part, a2, b2s, 0, 0.f, false, 0, 0, 0, 0, 0.f); __syncthreads();
            gemm16<1>(g_W3F, a2, part, 0, 0, 0, 0.f, false, hT, yT, ka, b3s, dt); __syncthreads();
            // stage 2: f(tt+dt/2, yT)
            gemm16<0>(g_W1F, yT, part, a1, b1s, w1ls, tt + 0.5f * dt, true, 0, 0, 0, 0, 0.f); __syncthreads();
            gemm16<0>(g_W2F, a1, part, a2, b2s, 0, 0.f, false, 0, 0, 0, 0, 0.f); __syncthreads();
            gemm16<2>(g_W3F, a2, part, 0, 0, 0, 0.f, false, hT, yT, ka, b3s, dt); __syncthreads();
            // stage 3: f(tt+dt/2, yT)
            gemm16<0>(g_W1F, yT, part, a1, b1s, w1ls, tt + 0.5f * dt, true, 0, 0, 0, 0, 0.f); __syncthreads();
            gemm16<0>(g_W2F, a1, part, a2, b2s, 0, 0.f, false, 0, 0, 0, 0, 0.f); __syncthreads();
            gemm16<3>(g_W3F, a2, part, 0, 0, 0, 0.f, false, hT, yT, ka, b3s, dt); __syncthreads();
            // stage 4: f(tt+dt, yT)
            gemm16<0>(g_W1F, yT, part, a1, b1s, w1ls, tt + dt, true, 0, 0, 0, 0, 0.f); __syncthreads();
            gemm16<0>(g_W2F, a1, part, a2, b2s, 0, 0.f, false, 0, 0, 0, 0, 0.f); __syncthreads();
            gemm16<4>(g_W3F, a2, part, 0, 0, 0, 0.f, false, hT, yT, ka, b3s, dt); __syncthreads();
            tt += dt;
        }
    }
}

extern "C" void kernel_launch(void* const* d_in, const int* in_sizes, int n_in,
                              void* d_out, int out_size) {
    const float* x    = (const float*)d_in[0];
    const float* t    = (const float*)d_in[1];
    const float* mask = (const float*)d_in[2];
    const float* W_ih = (const float*)d_in[3];
    const float* W_hh = (const float*)d_in[4];
    const float* b_ih = (const float*)d_in[5];
    const float* b_hh = (const float*)d_in[6];
    const float* W1   = (const float*)d_in[7];
    const float* b1   = (const float*)d_in[8];
    const float* W2   = (const float*)d_in[9];
    const float* b2   = (const float*)d_in[10];
    const float* W3   = (const float*)d_in[11];
    const float* b3   = (const float*)d_in[12];
    float* out = (float*)d_out;

    prep_kernel<<<256, 256>>>(W_ih, W_hh, W1, W2, W3);

    const int smem_bytes = 39424 * sizeof(float);  // 157696
    cudaFuncSetAttribute(odernn_kernel,
                         cudaFuncAttributeMaxDynamicSharedMemorySize, smem_bytes);
    odernn_kernel<<<NCTA, NT, smem_bytes>>>(x, t, mask, b_ih, b_hh,
                                            b1, b2, b3, out);
}